// round 13
// baseline (speedup 1.0000x reference)
#include <cuda_runtime.h>
#include <cuda_fp16.h>
#include <cstdint>

#define NTOK 16384
#define DIN  1024
#define DH   256
#define DOUT 1024
#define NEXP 8

// static device scratch (no runtime allocation)
__device__ int    g_count[NEXP];
__device__ int    g_tok[NEXP * NTOK];
__device__ float  g_wt[NEXP * NTOK];
__device__ int    g_slot2[2 * NTOK];                 // per-token expert slots
__device__ __half g_Hh[(size_t)NEXP * NTOK * DH];    // hidden activations (fp16)
__device__ __half g_Yh[(size_t)NEXP * NTOK * DOUT];  // weighted expert outputs (fp16)

// ---------------- helpers ----------------
__device__ __forceinline__ uint32_t pkh2(float lo, float hi) {
    __half2 h = __floats2half2_rn(lo, hi);
    return *(uint32_t*)&h;
}

__device__ __forceinline__ void mma_f16(float* c, const uint32_t* a, const uint32_t* b) {
    asm volatile(
        "mma.sync.aligned.m16n8k16.row.col.f32.f16.f16.f32 "
        "{%0,%1,%2,%3}, {%4,%5,%6,%7}, {%8,%9}, {%0,%1,%2,%3};\n"
        : "+f"(c[0]), "+f"(c[1]), "+f"(c[2]), "+f"(c[3])
        : "r"(a[0]), "r"(a[1]), "r"(a[2]), "r"(a[3]), "r"(b[0]), "r"(b[1]));
}

// Tiling: block tile 128x256, 8 warps (2m x 4n), warp tile 64x64.
// Chunk = 32 k-halves = 16 b32 k-pair words. Double-buffered smem.
#define BM 128
#define BN 256
#define BKW 16
#define ASTR 20
#define BSTR 264
#define SMEM_WORDS (2 * BM * ASTR + 2 * BKW * BSTR)   // 13568
#define SMEM_BYTES (SMEM_WORDS * 4)                    // 54272

// ---------------- kernel: zero expert counters ----------------
__global__ void zcnt_kernel() { if (threadIdx.x < NEXP) g_count[threadIdx.x] = 0; }

// ---------------- gate: exact fp32 logits, top-2, softmax, scatter ----------------
__global__ void moe_gate_kernel(const float* __restrict__ x, const float* __restrict__ Wg,
                                const float* __restrict__ bg, float* __restrict__ gate_out, int N) {
    int warp = (blockIdx.x * blockDim.x + threadIdx.x) >> 5;
    int lane = threadIdx.x & 31;
    if (warp >= N) return;
    const float4* xr4 = (const float4*)(x + (size_t)warp * DIN);
    float acc[8];
#pragma unroll
    for (int e = 0; e < 8; e++) acc[e] = 0.f;
    for (int k4 = lane; k4 < DIN / 4; k4 += 32) {   // 8 iterations
        float4 xv = xr4[k4];
        const float4* wr = (const float4*)(Wg + (size_t)k4 * 32);
        float4 w0 = wr[0], w1 = wr[1], w2 = wr[2], w3 = wr[3];
        float4 w4 = wr[4], w5 = wr[5], w6 = wr[6], w7 = wr[7];
        acc[0] += xv.x * w0.x; acc[1] += xv.x * w0.y; acc[2] += xv.x * w0.z; acc[3] += xv.x * w0.w;
        acc[4] += xv.x * w1.x; acc[5] += xv.x * w1.y; acc[6] += xv.x * w1.z; acc[7] += xv.x * w1.w;
        acc[0] += xv.y * w2.x; acc[1] += xv.y * w2.y; acc[2] += xv.y * w2.z; acc[3] += xv.y * w2.w;
        acc[4] += xv.y * w3.x; acc[5] += xv.y * w3.y; acc[6] += xv.y * w3.z; acc[7] += xv.y * w3.w;
        acc[0] += xv.z * w4.x; acc[1] += xv.z * w4.y; acc[2] += xv.z * w4.z; acc[3] += xv.z * w4.w;
        acc[4] += xv.z * w5.x; acc[5] += xv.z * w5.y; acc[6] += xv.z * w5.z; acc[7] += xv.z * w5.w;
        acc[0] += xv.w * w6.x; acc[1] += xv.w * w6.y; acc[2] += xv.w * w6.z; acc[3] += xv.w * w6.w;
        acc[4] += xv.w * w7.x; acc[5] += xv.w * w7.y; acc[6] += xv.w * w7.z; acc[7] += xv.w * w7.w;
    }
#pragma unroll
    for (int off = 16; off; off >>= 1)
#pragma unroll
        for (int e = 0; e < 8; e++) acc[e] += __shfl_xor_sync(0xFFFFFFFFu, acc[e], off);
    if (lane == 0) {
        float lg[8];
#pragma unroll
        for (int e = 0; e < 8; e++) { lg[e] = acc[e] + bg[e]; gate_out[(size_t)warp * 8 + e] = lg[e]; }
        int i0 = 0; float m0 = lg[0];
#pragma unroll
        for (int e = 1; e < 8; e++) if (lg[e] > m0) { m0 = lg[e]; i0 = e; }
        int i1 = -1; float m1 = -1e30f;
#pragma unroll
        for (int e = 0; e < 8; e++) if (e != i0 && lg[e] > m1) { m1 = lg[e]; i1 = e; }
        float e1 = __expf(m1 - m0);
        float inv = 1.f / (1.f + e1);
        int p0 = atomicAdd(&g_count[i0], 1);
        g_tok[i0 * NTOK + p0] = warp; g_wt[i0 * NTOK + p0] = inv;
        g_slot2[2 * warp + 0] = i0 * NTOK + p0;
        int p1 = atomicAdd(&g_count[i1], 1);
        g_tok[i1 * NTOK + p1] = warp; g_wt[i1 * NTOK + p1] = e1 * inv;
        g_slot2[2 * warp + 1] = i1 * NTOK + p1;
    }
}

// ---------------- GEMM1: g_Hh = relu(X[gathered] @ W1 + b1), K=1024, Ncols=256 ---
__global__ void __launch_bounds__(256, 1)
moe_gemm1(const float* __restrict__ x, const float* __restrict__ W1,
          const float* __restrict__ b1) {
    int e = blockIdx.z, m0 = blockIdx.y * BM;
    int M = g_count[e];
    if (m0 >= M) return;

    extern __shared__ uint32_t smem[];
    uint32_t (*As)[ASTR] = (uint32_t(*)[ASTR])smem;                    // [2*BM]
    uint32_t (*Bs)[BSTR] = (uint32_t(*)[BSTR])(smem + 2 * BM * ASTR);  // [2*BKW]

    int tid = threadIdx.x, wid = tid >> 5, lane = tid & 31;
    int wm = wid & 1, wn = wid >> 1;
    int g = lane >> 2, t = lane & 3;

    int ar = tid & 127, aw = (tid >> 7) * 8, acf = (tid >> 7) * 16;
    bool aval = (m0 + ar < M);
    const float* arow = x + (size_t)(aval ? g_tok[e * NTOK + m0 + ar] : 0) * DIN + acf;
    int kp = tid >> 4, nb4 = (tid & 15) * 4;
    const float* b0p = W1 + (size_t)e * DIN * DH + (size_t)(2 * kp) * DH + nb4;
    const float* b1p = b0p + DH;

    float acc[4][8][4];
#pragma unroll
    for (int i = 0; i < 4; i++)
#pragma unroll
        for (int j = 0; j < 8; j++)
#pragma unroll
            for (int q = 0; q < 4; q++) acc[i][j][q] = 0.f;

    float4 av[4], bv0[4], bv1[4];

#define LDCHUNK(kc) do {                                                    \
        int _k0 = (kc) * 32;                                                \
        _Pragma("unroll")                                                   \
        for (int q = 0; q < 4; q++)                                         \
            av[q] = aval ? *(const float4*)(arow + _k0 + q * 4)             \
                         : make_float4(0.f, 0.f, 0.f, 0.f);                 \
        size_t _bo = (size_t)_k0 * DH;                                      \
        _Pragma("unroll")                                                   \
        for (int q = 0; q < 4; q++) {                                       \
            bv0[q] = *(const float4*)(b0p + _bo + q * 64);                  \
            bv1[q] = *(const float4*)(b1p + _bo + q * 64);                  \
        }                                                                   \
    } while (0)

#define STCHUNK(bi) do {                                                    \
        uint4 _w0, _w1;                                                     \
        _w0.x = pkh2(av[0].x, av[0].y); _w0.y = pkh2(av[0].z, av[0].w);     \
        _w0.z = pkh2(av[1].x, av[1].y); _w0.w = pkh2(av[1].z, av[1].w);     \
        _w1.x = pkh2(av[2].x, av[2].y); _w1.y = pkh2(av[2].z, av[2].w);     \
        _w1.z = pkh2(av[3].x, av[3].y); _w1.w = pkh2(av[3].z, av[3].w);     \
        *(uint4*)&As[(bi) * BM + ar][aw + 0] = _w0;                         \
        *(uint4*)&As[(bi) * BM + ar][aw + 4] = _w1;                         \
        _Pragma("unroll")                                                   \
        for (int q = 0; q < 4; q++) {                                       \
            uint4 _w;                                                       \
            _w.x = pkh2(bv0[q].x, bv1[q].x);                                \
            _w.y = pkh2(bv0[q].y, bv1[q].y);                                \
            _w.z = pkh2(bv0[q].z, bv1[q].z);                                \
            _w.w = pkh2(bv0[q].w, bv1[q].w);                                \
            *(uint4*)&Bs[(bi) * BKW + kp][nb4 + q * 64] = _w;               \
        }                                                                   \
    } while (0)

    const int NK = DIN / 32;   // 32 chunks
    LDCHUNK(0);
    STCHUNK(0);
    LDCHUNK(1);
    __syncthreads();

    for (int kc = 0; kc < NK; kc++) {
        if (kc + 1 < NK) {
            STCHUNK((kc + 1) & 1);
            if (kc + 2 < NK) LDCHUNK(kc + 2);
        }
        int ab = (kc & 1) * BM, bb = (kc & 1) * BKW;
#pragma unroll
        for (int kk = 0; kk < 2; kk++) {
            int kb = kk * 8;
            uint32_t af[4][4], bf[8][2];
#pragma unroll
            for (int i = 0; i < 4; i++) {
                int rb = ab + wm * 64 + i * 16;
                af[i][0] = As[rb + g][kb + t];
                af[i][1] = As[rb + g + 8][kb + t];
                af[i][2] = As[rb + g][kb + t + 4];
                af[i][3] = As[rb + g + 8][kb + t + 4];
            }
#pragma unroll
            for (int j = 0; j < 8; j++) {
                int cb = wn * 64 + j * 8;
                bf[j][0] = Bs[bb + kb + t][cb + g];
                bf[j][1] = Bs[bb + kb + t + 4][cb + g];
            }
#pragma unroll
            for (int i = 0; i < 4; i++)
#pragma unroll
                for (int j = 0; j < 8; j++)
                    mma_f16(acc[i][j], af[i], bf[j]);
        }
        __syncthreads();
    }
#undef LDCHUNK
#undef STCHUNK

    // epilogue: relu(acc + bias) -> g_Hh (fp16)
#pragma unroll
    for (int i = 0; i < 4; i++) {
        int r0 = m0 + wm * 64 + i * 16 + g;
        int r1 = r0 + 8;
#pragma unroll
        for (int j = 0; j < 8; j++) {
            int col = wn * 64 + j * 8 + 2 * t;
            float bx = b1[(size_t)e * DH + col];
            float by = b1[(size_t)e * DH + col + 1];
            if (r0 < M) {
                *(uint32_t*)(g_Hh + ((size_t)e * NTOK + r0) * DH + col) =
                    pkh2(fmaxf(acc[i][j][0] + bx, 0.f), fmaxf(acc[i][j][1] + by, 0.f));
            }
            if (r1 < M) {
                *(uint32_t*)(g_Hh + ((size_t)e * NTOK + r1) * DH + col) =
                    pkh2(fmaxf(acc[i][j][2] + bx, 0.f), fmaxf(acc[i][j][3] + by, 0.f));
            }
        }
    }
}

// ---------------- GEMM2: g_Yh[slot] = wt*(Hh @ W2 + b2), K=256, Ncols=1024 --------
__global__ void __launch_bounds__(256, 1)
moe_gemm2(const float* __restrict__ W2, const float* __restrict__ b2) {
    int e = blockIdx.z, m0 = blockIdx.y * BM, n0 = blockIdx.x * BN;
    int M = g_count[e];
    if (m0 >= M) return;

    extern __shared__ uint32_t smem[];
    uint32_t (*As)[ASTR] = (uint32_t(*)[ASTR])smem;
    uint32_t (*Bs)[BSTR] = (uint32_t(*)[BSTR])(smem + 2 * BM * ASTR);

    int tid = threadIdx.x, wid = tid >> 5, lane = tid & 31;
    int wm = wid & 1, wn = wid >> 1;
    int g = lane >> 2, t = lane & 3;

    int ar = tid & 127, aw = (tid >> 7) * 8;
    bool aval = (m0 + ar < M);
    const uint4* ahb = (const uint4*)(g_Hh + ((size_t)e * NTOK + (m0 + ar)) * DH);
    int au = (tid >> 7) * 2;
    int kp = tid >> 4, nb4 = (tid & 15) * 4;
    const float* b0p = W2 + (size_t)e * DH * DOUT + (size_t)(2 * kp) * DOUT + n0 + nb4;
    const float* b1p = b0p + DOUT;

    float acc[4][8][4];
#pragma unroll
    for (int i = 0; i < 4; i++)
#pragma unroll
        for (int j = 0; j < 8; j++)
#pragma unroll
            for (int q = 0; q < 4; q++) acc[i][j][q] = 0.f;

    uint4 ah0, ah1;
    float4 bv0[4], bv1[4];

#define LDCHUNK(kc) do {                                                    \
        int _i = (kc) * 4 + au;                                             \
        ah0 = aval ? ahb[_i]     : make_uint4(0u, 0u, 0u, 0u);              \
        ah1 = aval ? ahb[_i + 1] : make_uint4(0u, 0u, 0u, 0u);              \
        size_t _bo = (size_t)(kc) * 32 * DOUT;                              \
        _Pragma("unroll")                                                   \
        for (int q = 0; q < 4; q++) {                                       \
            bv0[q] = *(const float4*)(b0p + _bo + q * 64);                  \
            bv1[q] = *(const float4*)(b1p + _bo + q * 64);                  \
        }                                                                   \
    } while (0)

#define STCHUNK(bi) do {                                                    \
        *(uint4*)&As[(bi) * BM + ar][aw + 0] = ah0;                         \
        *(uint4*)&As[(bi) * BM + ar][aw + 4] = ah1;                         \
        _Pragma("unroll")                                                   \
        for (int q = 0; q < 4; q++) {                                       \
            uint4 _w;                                                       \
            _w.x = pkh2(bv0[q].x, bv1[q].x);                                \
            _w.y = pkh2(bv0[q].y, bv1[q].y);                                \
            _w.z = pkh2(bv0[q].z, bv1[q].z);                                \
            _w.w = pkh2(bv0[q].w, bv1[q].w);                                \
            *(uint4*)&Bs[(bi) * BKW + kp][nb4 + q * 64] = _w;               \
        }                                                                   \
    } while (0)

    const int NK = DH / 32;    // 8 chunks
    LDCHUNK(0);
    STCHUNK(0);
    LDCHUNK(1);
    __syncthreads();

    for (int kc = 0; kc < NK; kc++) {
        if (kc + 1 < NK) {
            STCHUNK((kc + 1) & 1);
            if (kc + 2 < NK) LDCHUNK(kc + 2);
        }
        int ab = (kc & 1) * BM, bb = (kc & 1) * BKW;
#pragma unroll
        for (int kk = 0; kk < 2; kk++) {
            int kb = kk * 8;
            uint32_t af[4][4], bf[8][2];
#pragma unroll
            for (int i = 0; i < 4; i++) {
                int rb = ab + wm * 64 + i * 16;
                af[i][0] = As[rb + g][kb + t];
                af[i][1] = As[rb + g + 8][kb + t];
                af[i][2] = As[rb + g][kb + t + 4];
                af[i][3] = As[rb + g + 8][kb + t + 4];
            }
#pragma unroll
            for (int j = 0; j < 8; j++) {
                int cb = wn * 64 + j * 8;
                bf[j][0] = Bs[bb + kb + t][cb + g];
                bf[j][1] = Bs[bb + kb + t + 4][cb + g];
            }
#pragma unroll
            for (int i = 0; i < 4; i++)
#pragma unroll
                for (int j = 0; j < 8; j++)
                    mma_f16(acc[i][j], af[i], bf[j]);
        }
        __syncthreads();
    }
#undef LDCHUNK
#undef STCHUNK

    // epilogue: g_Yh[slot] = fp16(wt * (acc + bias))
#pragma unroll
    for (int i = 0; i < 4; i++) {
        int r0 = m0 + wm * 64 + i * 16 + g;
        int r1 = r0 + 8;
        float w0 = (r0 < M) ? g_wt[e * NTOK + r0] : 0.f;
        float w1 = (r1 < M) ? g_wt[e * NTOK + r1] : 0.f;
#pragma unroll
        for (int j = 0; j < 8; j++) {
            int col = n0 + wn * 64 + j * 8 + 2 * t;
            float bx = b2[(size_t)e * DOUT + col];
            float by = b2[(size_t)e * DOUT + col + 1];
            if (r0 < M) {
                *(uint32_t*)(g_Yh + ((size_t)e * NTOK + r0) * DOUT + col) =
                    pkh2(w0 * (acc[i][j][0] + bx), w0 * (acc[i][j][1] + by));
            }
            if (r1 < M) {
                *(uint32_t*)(g_Yh + ((size_t)e * NTOK + r1) * DOUT + col) =
                    pkh2(w1 * (acc[i][j][2] + bx), w1 * (acc[i][j][3] + by));
            }
        }
    }
}

// ---------------- combine: out[tok] = Yh[slotA] + Yh[slotB]  (2 tokens/block) -----
__global__ void combine_kernel(float* __restrict__ out) {
    int tid = threadIdx.x;
    int tok = blockIdx.x * 2;
#pragma unroll
    for (int s = 0; s < 2; s++, tok++) {
        int sa = g_slot2[2 * tok], sb = g_slot2[2 * tok + 1];
        uint2 ua = ((const uint2*)(g_Yh + (size_t)sa * DOUT))[tid];
        uint2 ub = ((const uint2*)(g_Yh + (size_t)sb * DOUT))[tid];
        float2 a0 = __half22float2(*(__half2*)&ua.x);
        float2 a1 = __half22float2(*(__half2*)&ua.y);
        float2 b0 = __half22float2(*(__half2*)&ub.x);
        float2 b1 = __half22float2(*(__half2*)&ub.y);
        float4 o = make_float4(a0.x + b0.x, a0.y + b0.y, a1.x + b1.x, a1.y + b1.y);
        ((float4*)(out + (size_t)tok * DOUT))[tid] = o;
    }
}

// ---------------- launch ----------------
extern "C" void kernel_launch(void* const* d_in, const int* in_sizes, int n_in,
                              void* d_out, int out_size) {
    const float* x  = (const float*)d_in[0];
    const float* Wg = (const float*)d_in[1];
    const float* bg = (const float*)d_in[2];
    const float* W1 = (const float*)d_in[3];
    const float* b1 = (const float*)d_in[4];
    const float* W2 = (const float*)d_in[5];
    const float* b2 = (const float*)d_in[6];

    int N = in_sizes[0] / DIN;   // 16384
    float* out      = (float*)d_out;
    float* gate_out = (float*)d_out + (size_t)N * DOUT;

    cudaFuncSetAttribute(moe_gemm1, cudaFuncAttributeMaxDynamicSharedMemorySize, SMEM_BYTES);
    cudaFuncSetAttribute(moe_gemm2, cudaFuncAttributeMaxDynamicSharedMemorySize, SMEM_BYTES);

    zcnt_kernel<<<1, 32>>>();
    moe_gate_kernel<<<(N * 32 + 255) / 256, 256>>>(x, Wg, bg, gate_out, N);

    dim3 g1(1, NTOK / BM, NEXP);          // 1 x 128 x 8
    moe_gemm1<<<g1, 256, SMEM_BYTES>>>(x, W1, b1);

    dim3 g2(DOUT / BN, NTOK / BM, NEXP);  // 4 x 128 x 8
    moe_gemm2<<<g2, 256, SMEM_BYTES>>>(W2, b2);

    combine_kernel<<<N / 2, 256>>>(out);
}

// round 14
// speedup vs baseline: 1.2281x; 1.2281x over previous
#include <cuda_runtime.h>
#include <cuda_fp16.h>
#include <cstdint>

#define NTOK 16384
#define DIN  1024
#define DH   256
#define DOUT 1024
#define NEXP 8

// static device scratch (no runtime allocation)
__device__ int    g_count[NEXP];
__device__ int    g_tok[NEXP * NTOK];
__device__ float  g_wt[NEXP * NTOK];
__device__ int    g_slot2[2 * NTOK];                 // per-token expert slots
__device__ __half g_Hh[(size_t)NEXP * NTOK * DH];    // hidden activations (fp16)
__device__ __half g_Yh[(size_t)NEXP * NTOK * DOUT];  // weighted expert outputs (fp16)

// ---------------- helpers ----------------
__device__ __forceinline__ uint32_t pkh2(float lo, float hi) {
    __half2 h = __floats2half2_rn(lo, hi);
    return *(uint32_t*)&h;
}

__device__ __forceinline__ void mma_f16(float* c, const uint32_t* a, const uint32_t* b) {
    asm volatile(
        "mma.sync.aligned.m16n8k16.row.col.f32.f16.f16.f32 "
        "{%0,%1,%2,%3}, {%4,%5,%6,%7}, {%8,%9}, {%0,%1,%2,%3};\n"
        : "+f"(c[0]), "+f"(c[1]), "+f"(c[2]), "+f"(c[3])
        : "r"(a[0]), "r"(a[1]), "r"(a[2]), "r"(a[3]), "r"(b[0]), "r"(b[1]));
}

// Tiling: block tile 128x256, 8 warps (2m x 4n), warp tile 64x64.
// Chunk = 32 k-halves = 16 b32 k-pair words. Double-buffered smem.
#define BM 128
#define BN 256
#define BKW 16
#define ASTR 20
#define BSTR 264
#define SMEM_WORDS (2 * BM * ASTR + 2 * BKW * BSTR)   // 13568
#define SMEM_BYTES (SMEM_WORDS * 4)                    // 54272

// ---------------- kernel: zero expert counters ----------------
__global__ void zcnt_kernel() { if (threadIdx.x < NEXP) g_count[threadIdx.x] = 0; }

// ---------------- gate: exact fp32 logits, top-2, softmax, scatter (R12 verbatim) -
__global__ void moe_gate_kernel(const float* __restrict__ x, const float* __restrict__ Wg,
                                const float* __restrict__ bg, float* __restrict__ gate_out, int N) {
    int warp = (blockIdx.x * blockDim.x + threadIdx.x) >> 5;
    int lane = threadIdx.x & 31;
    if (warp >= N) return;
    const float* xr = x + (size_t)warp * DIN;
    float acc[8];
#pragma unroll
    for (int e = 0; e < 8; e++) acc[e] = 0.f;
    for (int k = lane; k < DIN; k += 32) {
        float xv = xr[k];
        const float4* wrow = (const float4*)(Wg + (size_t)k * 8);
        float4 w0 = wrow[0], w1 = wrow[1];
        acc[0] += xv * w0.x; acc[1] += xv * w0.y; acc[2] += xv * w0.z; acc[3] += xv * w0.w;
        acc[4] += xv * w1.x; acc[5] += xv * w1.y; acc[6] += xv * w1.z; acc[7] += xv * w1.w;
    }
#pragma unroll
    for (int off = 16; off; off >>= 1)
#pragma unroll
        for (int e = 0; e < 8; e++) acc[e] += __shfl_xor_sync(0xFFFFFFFFu, acc[e], off);
    if (lane == 0) {
        float lg[8];
#pragma unroll
        for (int e = 0; e < 8; e++) { lg[e] = acc[e] + bg[e]; gate_out[(size_t)warp * 8 + e] = lg[e]; }
        int i0 = 0; float m0 = lg[0];
#pragma unroll
        for (int e = 1; e < 8; e++) if (lg[e] > m0) { m0 = lg[e]; i0 = e; }
        int i1 = -1; float m1 = -1e30f;
#pragma unroll
        for (int e = 0; e < 8; e++) if (e != i0 && lg[e] > m1) { m1 = lg[e]; i1 = e; }
        float e1 = __expf(m1 - m0);
        float inv = 1.f / (1.f + e1);
        int p0 = atomicAdd(&g_count[i0], 1);
        g_tok[i0 * NTOK + p0] = warp; g_wt[i0 * NTOK + p0] = inv;
        g_slot2[2 * warp + 0] = i0 * NTOK + p0;
        int p1 = atomicAdd(&g_count[i1], 1);
        g_tok[i1 * NTOK + p1] = warp; g_wt[i1 * NTOK + p1] = e1 * inv;
        g_slot2[2 * warp + 1] = i1 * NTOK + p1;
    }
}

// ---------------- GEMM1: g_Hh = relu(X[gathered] @ W1 + b1), K=1024, Ncols=256 ---
__global__ void __launch_bounds__(256, 1)
moe_gemm1(const float* __restrict__ x, const float* __restrict__ W1,
          const float* __restrict__ b1) {
    int e = blockIdx.z, m0 = blockIdx.y * BM;
    int M = g_count[e];
    if (m0 >= M) return;

    extern __shared__ uint32_t smem[];
    uint32_t (*As)[ASTR] = (uint32_t(*)[ASTR])smem;                    // [2*BM]
    uint32_t (*Bs)[BSTR] = (uint32_t(*)[BSTR])(smem + 2 * BM * ASTR);  // [2*BKW]

    int tid = threadIdx.x, wid = tid >> 5, lane = tid & 31;
    int wm = wid & 1, wn = wid >> 1;
    int g = lane >> 2, t = lane & 3;

    int ar = tid & 127, aw = (tid >> 7) * 8, acf = (tid >> 7) * 16;
    bool aval = (m0 + ar < M);
    const float* arow = x + (size_t)(aval ? g_tok[e * NTOK + m0 + ar] : 0) * DIN + acf;
    int kp = tid >> 4, nb4 = (tid & 15) * 4;
    const float* b0p = W1 + (size_t)e * DIN * DH + (size_t)(2 * kp) * DH + nb4;
    const float* b1p = b0p + DH;

    float acc[4][8][4];
#pragma unroll
    for (int i = 0; i < 4; i++)
#pragma unroll
        for (int j = 0; j < 8; j++)
#pragma unroll
            for (int q = 0; q < 4; q++) acc[i][j][q] = 0.f;

    float4 av[4], bv0[4], bv1[4];

#define LDCHUNK(kc) do {                                                    \
        int _k0 = (kc) * 32;                                                \
        _Pragma("unroll")                                                   \
        for (int q = 0; q < 4; q++)                                         \
            av[q] = aval ? *(const float4*)(arow + _k0 + q * 4)             \
                         : make_float4(0.f, 0.f, 0.f, 0.f);                 \
        size_t _bo = (size_t)_k0 * DH;                                      \
        _Pragma("unroll")                                                   \
        for (int q = 0; q < 4; q++) {                                       \
            bv0[q] = *(const float4*)(b0p + _bo + q * 64);                  \
            bv1[q] = *(const float4*)(b1p + _bo + q * 64);                  \
        }                                                                   \
    } while (0)

#define STCHUNK(bi) do {                                                    \
        uint4 _w0, _w1;                                                     \
        _w0.x = pkh2(av[0].x, av[0].y); _w0.y = pkh2(av[0].z, av[0].w);     \
        _w0.z = pkh2(av[1].x, av[1].y); _w0.w = pkh2(av[1].z, av[1].w);     \
        _w1.x = pkh2(av[2].x, av[2].y); _w1.y = pkh2(av[2].z, av[2].w);     \
        _w1.z = pkh2(av[3].x, av[3].y); _w1.w = pkh2(av[3].z, av[3].w);     \
        *(uint4*)&As[(bi) * BM + ar][aw + 0] = _w0;                         \
        *(uint4*)&As[(bi) * BM + ar][aw + 4] = _w1;                         \
        _Pragma("unroll")                                                   \
        for (int q = 0; q < 4; q++) {                                       \
            uint4 _w;                                                       \
            _w.x = pkh2(bv0[q].x, bv1[q].x);                                \
            _w.y = pkh2(bv0[q].y, bv1[q].y);                                \
            _w.z = pkh2(bv0[q].z, bv1[q].z);                                \
            _w.w = pkh2(bv0[q].w, bv1[q].w);                                \
            *(uint4*)&Bs[(bi) * BKW + kp][nb4 + q * 64] = _w;               \
        }                                                                   \
    } while (0)

    const int NK = DIN / 32;   // 32 chunks
    LDCHUNK(0);
    STCHUNK(0);
    LDCHUNK(1);
    __syncthreads();

    for (int kc = 0; kc < NK; kc++) {
        if (kc + 1 < NK) {
            STCHUNK((kc + 1) & 1);
            if (kc + 2 < NK) LDCHUNK(kc + 2);
        }
        int ab = (kc & 1) * BM, bb = (kc & 1) * BKW;
#pragma unroll
        for (int kk = 0; kk < 2; kk++) {
            int kb = kk * 8;
            uint32_t af[4][4], bf[8][2];
#pragma unroll
            for (int i = 0; i < 4; i++) {
                int rb = ab + wm * 64 + i * 16;
                af[i][0] = As[rb + g][kb + t];
                af[i][1] = As[rb + g + 8][kb + t];
                af[i][2] = As[rb + g][kb + t + 4];
                af[i][3] = As[rb + g + 8][kb + t + 4];
            }
#pragma unroll
            for (int j = 0; j < 8; j++) {
                int cb = wn * 64 + j * 8;
                bf[j][0] = Bs[bb + kb + t][cb + g];
                bf[j][1] = Bs[bb + kb + t + 4][cb + g];
            }
#pragma unroll
            for (int i = 0; i < 4; i++)
#pragma unroll
                for (int j = 0; j < 8; j++)
                    mma_f16(acc[i][j], af[i], bf[j]);
        }
        __syncthreads();
    }
#undef LDCHUNK
#undef STCHUNK

    // epilogue: relu(acc + bias) -> g_Hh (fp16)
#pragma unroll
    for (int i = 0; i < 4; i++) {
        int r0 = m0 + wm * 64 + i * 16 + g;
        int r1 = r0 + 8;
#pragma unroll
        for (int j = 0; j < 8; j++) {
            int col = wn * 64 + j * 8 + 2 * t;
            float bx = b1[(size_t)e * DH + col];
            float by = b1[(size_t)e * DH + col + 1];
            if (r0 < M) {
                *(uint32_t*)(g_Hh + ((size_t)e * NTOK + r0) * DH + col) =
                    pkh2(fmaxf(acc[i][j][0] + bx, 0.f), fmaxf(acc[i][j][1] + by, 0.f));
            }
            if (r1 < M) {
                *(uint32_t*)(g_Hh + ((size_t)e * NTOK + r1) * DH + col) =
                    pkh2(fmaxf(acc[i][j][2] + bx, 0.f), fmaxf(acc[i][j][3] + by, 0.f));
            }
        }
    }
}

// ---------------- GEMM2: g_Yh[slot] = wt*(Hh @ W2 + b2), K=256, Ncols=1024 --------
__global__ void __launch_bounds__(256, 1)
moe_gemm2(const float* __restrict__ W2, const float* __restrict__ b2) {
    int e = blockIdx.z, m0 = blockIdx.y * BM, n0 = blockIdx.x * BN;
    int M = g_count[e];
    if (m0 >= M) return;

    extern __shared__ uint32_t smem[];
    uint32_t (*As)[ASTR] = (uint32_t(*)[ASTR])smem;
    uint32_t (*Bs)[BSTR] = (uint32_t(*)[BSTR])(smem + 2 * BM * ASTR);

    int tid = threadIdx.x, wid = tid >> 5, lane = tid & 31;
    int wm = wid & 1, wn = wid >> 1;
    int g = lane >> 2, t = lane & 3;

    int ar = tid & 127, aw = (tid >> 7) * 8;
    bool aval = (m0 + ar < M);
    const uint4* ahb = (const uint4*)(g_Hh + ((size_t)e * NTOK + (m0 + ar)) * DH);
    int au = (tid >> 7) * 2;
    int kp = tid >> 4, nb4 = (tid & 15) * 4;
    const float* b0p = W2 + (size_t)e * DH * DOUT + (size_t)(2 * kp) * DOUT + n0 + nb4;
    const float* b1p = b0p + DOUT;

    float acc[4][8][4];
#pragma unroll
    for (int i = 0; i < 4; i++)
#pragma unroll
        for (int j = 0; j < 8; j++)
#pragma unroll
            for (int q = 0; q < 4; q++) acc[i][j][q] = 0.f;

    uint4 ah0, ah1;
    float4 bv0[4], bv1[4];

#define LDCHUNK(kc) do {                                                    \
        int _i = (kc) * 4 + au;                                             \
        ah0 = aval ? ahb[_i]     : make_uint4(0u, 0u, 0u, 0u);              \
        ah1 = aval ? ahb[_i + 1] : make_uint4(0u, 0u, 0u, 0u);              \
        size_t _bo = (size_t)(kc) * 32 * DOUT;                              \
        _Pragma("unroll")                                                   \
        for (int q = 0; q < 4; q++) {                                       \
            bv0[q] = *(const float4*)(b0p + _bo + q * 64);                  \
            bv1[q] = *(const float4*)(b1p + _bo + q * 64);                  \
        }                                                                   \
    } while (0)

#define STCHUNK(bi) do {                                                    \
        *(uint4*)&As[(bi) * BM + ar][aw + 0] = ah0;                         \
        *(uint4*)&As[(bi) * BM + ar][aw + 4] = ah1;                         \
        _Pragma("unroll")                                                   \
        for (int q = 0; q < 4; q++) {                                       \
            uint4 _w;                                                       \
            _w.x = pkh2(bv0[q].x, bv1[q].x);                                \
            _w.y = pkh2(bv0[q].y, bv1[q].y);                                \
            _w.z = pkh2(bv0[q].z, bv1[q].z);                                \
            _w.w = pkh2(bv0[q].w, bv1[q].w);                                \
            *(uint4*)&Bs[(bi) * BKW + kp][nb4 + q * 64] = _w;               \
        }                                                                   \
    } while (0)

    const int NK = DH / 32;    // 8 chunks
    LDCHUNK(0);
    STCHUNK(0);
    LDCHUNK(1);
    __syncthreads();

    for (int kc = 0; kc < NK; kc++) {
        if (kc + 1 < NK) {
            STCHUNK((kc + 1) & 1);
            if (kc + 2 < NK) LDCHUNK(kc + 2);
        }
        int ab = (kc & 1) * BM, bb = (kc & 1) * BKW;
#pragma unroll
        for (int kk = 0; kk < 2; kk++) {
            int kb = kk * 8;
            uint32_t af[4][4], bf[8][2];
#pragma unroll
            for (int i = 0; i < 4; i++) {
                int rb = ab + wm * 64 + i * 16;
                af[i][0] = As[rb + g][kb + t];
                af[i][1] = As[rb + g + 8][kb + t];
                af[i][2] = As[rb + g][kb + t + 4];
                af[i][3] = As[rb + g + 8][kb + t + 4];
            }
#pragma unroll
            for (int j = 0; j < 8; j++) {
                int cb = wn * 64 + j * 8;
                bf[j][0] = Bs[bb + kb + t][cb + g];
                bf[j][1] = Bs[bb + kb + t + 4][cb + g];
            }
#pragma unroll
            for (int i = 0; i < 4; i++)
#pragma unroll
                for (int j = 0; j < 8; j++)
                    mma_f16(acc[i][j], af[i], bf[j]);
        }
        __syncthreads();
    }
#undef LDCHUNK
#undef STCHUNK

    // epilogue: g_Yh[slot] = fp16(wt * (acc + bias))
#pragma unroll
    for (int i = 0; i < 4; i++) {
        int r0 = m0 + wm * 64 + i * 16 + g;
        int r1 = r0 + 8;
        float w0 = (r0 < M) ? g_wt[e * NTOK + r0] : 0.f;
        float w1 = (r1 < M) ? g_wt[e * NTOK + r1] : 0.f;
#pragma unroll
        for (int j = 0; j < 8; j++) {
            int col = n0 + wn * 64 + j * 8 + 2 * t;
            float bx = b2[(size_t)e * DOUT + col];
            float by = b2[(size_t)e * DOUT + col + 1];
            if (r0 < M) {
                *(uint32_t*)(g_Yh + ((size_t)e * NTOK + r0) * DOUT + col) =
                    pkh2(w0 * (acc[i][j][0] + bx), w0 * (acc[i][j][1] + by));
            }
            if (r1 < M) {
                *(uint32_t*)(g_Yh + ((size_t)e * NTOK + r1) * DOUT + col) =
                    pkh2(w1 * (acc[i][j][2] + bx), w1 * (acc[i][j][3] + by));
            }
        }
    }
}

// ---------------- combine: out[tok] = Yh[slotA] + Yh[slotB]  (R12 shape) ----------
__global__ void combine_kernel(float* __restrict__ out) {
    int tok = blockIdx.x, tid = threadIdx.x;
    int sa = g_slot2[2 * tok], sb = g_slot2[2 * tok + 1];
    uint2 ua = ((const uint2*)(g_Yh + (size_t)sa * DOUT))[tid];
    uint2 ub = ((const uint2*)(g_Yh + (size_t)sb * DOUT))[tid];
    float2 a0 = __half22float2(*(__half2*)&ua.x);
    float2 a1 = __half22float2(*(__half2*)&ua.y);
    float2 b0 = __half22float2(*(__half2*)&ub.x);
    float2 b1 = __half22float2(*(__half2*)&ub.y);
    ((float4*)(out + (size_t)tok * DOUT))[tid] =
        make_float4(a0.x + b0.x, a0.y + b0.y, a1.x + b1.x, a1.y + b1.y);
}

// ---------------- launch ----------------
extern "C" void kernel_launch(void* const* d_in, const int* in_sizes, int n_in,
                              void* d_out, int out_size) {
    const float* x  = (const float*)d_in[0];
    const float* Wg = (const float*)d_in[1];
    const float* bg = (const float*)d_in[2];
    const float* W1 = (const float*)d_in[3];
    const float* b1 = (const float*)d_in[4];
    const float* W2 = (const float*)d_in[5];
    const float* b2 = (const float*)d_in[6];

    int N = in_sizes[0] / DIN;   // 16384
    float* out      = (float*)d_out;
    float* gate_out = (float*)d_out + (size_t)N * DOUT;

    cudaFuncSetAttribute(moe_gemm1, cudaFuncAttributeMaxDynamicSharedMemorySize, SMEM_BYTES);
    cudaFuncSetAttribute(moe_gemm2, cudaFuncAttributeMaxDynamicSharedMemorySize, SMEM_BYTES);

    zcnt_kernel<<<1, 32>>>();
    moe_gate_kernel<<<(N * 32 + 255) / 256, 256>>>(x, Wg, bg, gate_out, N);

    dim3 g1(1, NTOK / BM, NEXP);          // 1 x 128 x 8
    moe_gemm1<<<g1, 256, SMEM_BYTES>>>(x, W1, b1);

    dim3 g2(DOUT / BN, NTOK / BM, NEXP);  // 4 x 128 x 8
    moe_gemm2<<<g2, 256, SMEM_BYTES>>>(W2, b2);

    combine_kernel<<<N, 256>>>(out);
}

// round 15
// speedup vs baseline: 1.3626x; 1.1096x over previous
#include <cuda_runtime.h>
#include <cuda_fp16.h>
#include <cstdint>

#define NTOK 16384
#define DIN  1024
#define DH   256
#define DOUT 1024
#define NEXP 8

// static device scratch (no runtime allocation)
__device__ int    g_count[NEXP];
__device__ int    g_tok[NEXP * NTOK];
__device__ float  g_wt[NEXP * NTOK];
__device__ int    g_slot2[2 * NTOK];                 // per-token expert slots
__device__ __half g_Yh[(size_t)NEXP * NTOK * DOUT];  // weighted expert outputs (fp16)

// ---------------- helpers ----------------
__device__ __forceinline__ uint32_t pkh2(float lo, float hi) {
    __half2 h = __floats2half2_rn(lo, hi);
    return *(uint32_t*)&h;
}

__device__ __forceinline__ void mma_f16(float* c, const uint32_t* a, const uint32_t* b) {
    asm volatile(
        "mma.sync.aligned.m16n8k16.row.col.f32.f16.f16.f32 "
        "{%0,%1,%2,%3}, {%4,%5,%6,%7}, {%8,%9}, {%0,%1,%2,%3};\n"
        : "+f"(c[0]), "+f"(c[1]), "+f"(c[2]), "+f"(c[3])
        : "r"(a[0]), "r"(a[1]), "r"(a[2]), "r"(a[3]), "r"(b[0]), "r"(b[1]));
}

// Tiling: block tile 128 tokens; 8 warps (2m x 4n), warp tile 64x64.
// Chunk = 32 k-halves = 16 b32 k-pair words. Double-buffered staging.
#define BM 128
#define BN 256
#define BKW 16
#define ASTR 20
#define BSTR 264
#define HSTR 132    // H smem row stride in words (128 + 4 pad; frag banks 4g+t distinct)
// smem words: As 2*128*20=5120, Bs 2*16*264=8448, Hs 128*132=16896
#define FFN_SMEM_WORDS (2 * BM * ASTR + 2 * BKW * BSTR + BM * HSTR)
#define FFN_SMEM_BYTES (FFN_SMEM_WORDS * 4)           // 121856

// ---------------- kernel: zero expert counters ----------------
__global__ void zcnt_kernel() { if (threadIdx.x < NEXP) g_count[threadIdx.x] = 0; }

// ---------------- gate: exact fp32 logits, top-2, softmax, scatter ----------------
__global__ void moe_gate_kernel(const float* __restrict__ x, const float* __restrict__ Wg,
                                const float* __restrict__ bg, float* __restrict__ gate_out, int N) {
    int warp = (blockIdx.x * blockDim.x + threadIdx.x) >> 5;
    int lane = threadIdx.x & 31;
    if (warp >= N) return;
    const float* xr = x + (size_t)warp * DIN;
    float acc[8];
#pragma unroll
    for (int e = 0; e < 8; e++) acc[e] = 0.f;
    for (int k = lane; k < DIN; k += 32) {
        float xv = xr[k];
        const float4* wrow = (const float4*)(Wg + (size_t)k * 8);
        float4 w0 = wrow[0], w1 = wrow[1];
        acc[0] += xv * w0.x; acc[1] += xv * w0.y; acc[2] += xv * w0.z; acc[3] += xv * w0.w;
        acc[4] += xv * w1.x; acc[5] += xv * w1.y; acc[6] += xv * w1.z; acc[7] += xv * w1.w;
    }
#pragma unroll
    for (int off = 16; off; off >>= 1)
#pragma unroll
        for (int e = 0; e < 8; e++) acc[e] += __shfl_xor_sync(0xFFFFFFFFu, acc[e], off);
    if (lane == 0) {
        float lg[8];
#pragma unroll
        for (int e = 0; e < 8; e++) { lg[e] = acc[e] + bg[e]; gate_out[(size_t)warp * 8 + e] = lg[e]; }
        int i0 = 0; float m0 = lg[0];
#pragma unroll
        for (int e = 1; e < 8; e++) if (lg[e] > m0) { m0 = lg[e]; i0 = e; }
        int i1 = -1; float m1 = -1e30f;
#pragma unroll
        for (int e = 0; e < 8; e++) if (e != i0 && lg[e] > m1) { m1 = lg[e]; i1 = e; }
        float e1 = __expf(m1 - m0);
        float inv = 1.f / (1.f + e1);
        int p0 = atomicAdd(&g_count[i0], 1);
        g_tok[i0 * NTOK + p0] = warp; g_wt[i0 * NTOK + p0] = inv;
        g_slot2[2 * warp + 0] = i0 * NTOK + p0;
        int p1 = atomicAdd(&g_count[i1], 1);
        g_tok[i1 * NTOK + p1] = warp; g_wt[i1 * NTOK + p1] = e1 * inv;
        g_slot2[2 * warp + 1] = i1 * NTOK + p1;
    }
}

// ---------------- fused FFN: per 128-token tile do
//   phase 1: H = relu(X[gathered] @ W1 + b1)  -> smem (fp16)
//   phase 2: for 4 n-tiles: g_Yh[slot] = fp16(wt * (H @ W2 + b2))
__global__ void __launch_bounds__(256, 1)
moe_ffn(const float* __restrict__ x, const float* __restrict__ W1,
        const float* __restrict__ b1, const float* __restrict__ W2,
        const float* __restrict__ b2) {
    int e = blockIdx.z, m0 = blockIdx.y * BM;
    int M = g_count[e];
    if (m0 >= M) return;

    extern __shared__ uint32_t smem[];
    uint32_t (*As)[ASTR] = (uint32_t(*)[ASTR])smem;                                // [2*BM]
    uint32_t (*Bs)[BSTR] = (uint32_t(*)[BSTR])(smem + 2 * BM * ASTR);              // [2*BKW]
    uint32_t (*Hs)[HSTR] = (uint32_t(*)[HSTR])(smem + 2 * BM * ASTR + 2 * BKW * BSTR); // [BM]

    int tid = threadIdx.x, wid = tid >> 5, lane = tid & 31;
    int wm = wid & 1, wn = wid >> 1;
    int g = lane >> 2, t = lane & 3;

    // ---- phase 1: X @ W1 (K = 1024) ----
    int ar = tid & 127, aw = (tid >> 7) * 8, acf = (tid >> 7) * 16;
    bool aval = (m0 + ar < M);
    const float* arow = x + (size_t)(aval ? g_tok[e * NTOK + m0 + ar] : 0) * DIN + acf;
    int kp = tid >> 4, nb4 = (tid & 15) * 4;
    const float* b0p = W1 + (size_t)e * DIN * DH + (size_t)(2 * kp) * DH + nb4;
    const float* b1p = b0p + DH;

    float acc[4][8][4];
#pragma unroll
    for (int i = 0; i < 4; i++)
#pragma unroll
        for (int j = 0; j < 8; j++)
#pragma unroll
            for (int q = 0; q < 4; q++) acc[i][j][q] = 0.f;

    float4 av[4], bv0[4], bv1[4];

#define LDCHUNK1(kc) do {                                                   \
        int _k0 = (kc) * 32;                                                \
        _Pragma("unroll")                                                   \
        for (int q = 0; q < 4; q++)                                         \
            av[q] = aval ? *(const float4*)(arow + _k0 + q * 4)             \
                         : make_float4(0.f, 0.f, 0.f, 0.f);                 \
        size_t _bo = (size_t)_k0 * DH;                                      \
        _Pragma("unroll")                                                   \
        for (int q = 0; q < 4; q++) {                                       \
            bv0[q] = *(const float4*)(b0p + _bo + q * 64);                  \
            bv1[q] = *(const float4*)(b1p + _bo + q * 64);                  \
        }                                                                   \
    } while (0)

#define STCHUNK1(bi) do {                                                   \
        uint4 _w0, _w1;                                                     \
        _w0.x = pkh2(av[0].x, av[0].y); _w0.y = pkh2(av[0].z, av[0].w);     \
        _w0.z = pkh2(av[1].x, av[1].y); _w0.w = pkh2(av[1].z, av[1].w);     \
        _w1.x = pkh2(av[2].x, av[2].y); _w1.y = pkh2(av[2].z, av[2].w);     \
        _w1.z = pkh2(av[3].x, av[3].y); _w1.w = pkh2(av[3].z, av[3].w);     \
        *(uint4*)&As[(bi) * BM + ar][aw + 0] = _w0;                         \
        *(uint4*)&As[(bi) * BM + ar][aw + 4] = _w1;                         \
        _Pragma("unroll")                                                   \
        for (int q = 0; q < 4; q++) {                                       \
            uint4 _w;                                                       \
            _w.x = pkh2(bv0[q].x, bv1[q].x);                                \
            _w.y = pkh2(bv0[q].y, bv1[q].y);                                \
            _w.z = pkh2(bv0[q].z, bv1[q].z);                                \
            _w.w = pkh2(bv0[q].w, bv1[q].w);                                \
            *(uint4*)&Bs[(bi) * BKW + kp][nb4 + q * 64] = _w;               \
        }                                                                   \
    } while (0)

    const int NK1 = DIN / 32;   // 32 chunks
    LDCHUNK1(0);
    STCHUNK1(0);
    LDCHUNK1(1);
    __syncthreads();

    for (int kc = 0; kc < NK1; kc++) {
        if (kc + 1 < NK1) {
            STCHUNK1((kc + 1) & 1);
            if (kc + 2 < NK1) LDCHUNK1(kc + 2);
        }
        int ab = (kc & 1) * BM, bb = (kc & 1) * BKW;
#pragma unroll
        for (int kk = 0; kk < 2; kk++) {
            int kb = kk * 8;
            uint32_t af[4][4], bf[8][2];
#pragma unroll
            for (int i = 0; i < 4; i++) {
                int rb = ab + wm * 64 + i * 16;
                af[i][0] = As[rb + g][kb + t];
                af[i][1] = As[rb + g + 8][kb + t];
                af[i][2] = As[rb + g][kb + t + 4];
                af[i][3] = As[rb + g + 8][kb + t + 4];
            }
#pragma unroll
            for (int j = 0; j < 8; j++) {
                int cb = wn * 64 + j * 8;
                bf[j][0] = Bs[bb + kb + t][cb + g];
                bf[j][1] = Bs[bb + kb + t + 4][cb + g];
            }
#pragma unroll
            for (int i = 0; i < 4; i++)
#pragma unroll
                for (int j = 0; j < 8; j++)
                    mma_f16(acc[i][j], af[i], bf[j]);
        }
        __syncthreads();
    }

    // phase-1 epilogue: relu(acc + b1) -> Hs (fp16 pairs; same rounding as R14 g_Hh)
#pragma unroll
    for (int i = 0; i < 4; i++) {
        int r0l = wm * 64 + i * 16 + g;
        int r1l = r0l + 8;
#pragma unroll
        for (int j = 0; j < 8; j++) {
            int col  = wn * 64 + j * 8 + 2 * t;       // half index in DH
            int wcol = wn * 32 + j * 4 + t;           // word index in DH
            float bx = b1[(size_t)e * DH + col];
            float by = b1[(size_t)e * DH + col + 1];
            Hs[r0l][wcol] = pkh2(fmaxf(acc[i][j][0] + bx, 0.f), fmaxf(acc[i][j][1] + by, 0.f));
            Hs[r1l][wcol] = pkh2(fmaxf(acc[i][j][2] + bx, 0.f), fmaxf(acc[i][j][3] + by, 0.f));
        }
    }
    __syncthreads();

    // ---- phase 2: H @ W2 (K = 256), 4 n-tiles of 256 ----
    const float* c0p = W2 + (size_t)e * DH * DOUT + (size_t)(2 * kp) * DOUT + nb4;
    const float* c1p = c0p + DOUT;

    // per-row token/weight (same rows for all n-tiles)
    int   tok0[4], tok1[4];
    float wt0[4], wt1[4];
#pragma unroll
    for (int i = 0; i < 4; i++) {
        int r0 = m0 + wm * 64 + i * 16 + g;
        int r1 = r0 + 8;
        tok0[i] = 0; tok1[i] = 0; wt0[i] = 0.f; wt1[i] = 0.f;
        if (r0 < M) { tok0[i] = r0; wt0[i] = g_wt[e * NTOK + r0]; }
        if (r1 < M) { tok1[i] = r1; wt1[i] = g_wt[e * NTOK + r1]; }
    }

#define LDCHUNK2(kc, n0) do {                                               \
        size_t _bo = (size_t)(kc) * 32 * DOUT + (n0);                       \
        _Pragma("unroll")                                                   \
        for (int q = 0; q < 4; q++) {                                       \
            bv0[q] = *(const float4*)(c0p + _bo + q * 64);                  \
            bv1[q] = *(const float4*)(c1p + _bo + q * 64);                  \
        }                                                                   \
    } while (0)

#define STCHUNK2(bi) do {                                                   \
        _Pragma("unroll")                                                   \
        for (int q = 0; q < 4; q++) {                                       \
            uint4 _w;                                                       \
            _w.x = pkh2(bv0[q].x, bv1[q].x);                                \
            _w.y = pkh2(bv0[q].y, bv1[q].y);                                \
            _w.z = pkh2(bv0[q].z, bv1[q].z);                                \
            _w.w = pkh2(bv0[q].w, bv1[q].w);                                \
            *(uint4*)&Bs[(bi) * BKW + kp][nb4 + q * 64] = _w;               \
        }                                                                   \
    } while (0)

    const int NK2 = DH / 32;    // 8 chunks
    for (int nt = 0; nt < 4; nt++) {
        int n0 = nt * BN;
#pragma unroll
        for (int i = 0; i < 4; i++)
#pragma unroll
            for (int j = 0; j < 8; j++)
#pragma unroll
                for (int q = 0; q < 4; q++) acc[i][j][q] = 0.f;

        LDCHUNK2(0, n0);
        STCHUNK2(0);
        LDCHUNK2(1, n0);
        __syncthreads();

        for (int kc = 0; kc < NK2; kc++) {
            if (kc + 1 < NK2) {
                STCHUNK2((kc + 1) & 1);
                if (kc + 2 < NK2) LDCHUNK2(kc + 2, n0);
            }
            int bb = (kc & 1) * BKW;
            int kw0 = kc * 16;
#pragma unroll
            for (int kk = 0; kk < 2; kk++) {
                int kb = kk * 8;
                uint32_t af[4][4], bf[8][2];
#pragma unroll
                for (int i = 0; i < 4; i++) {
                    int rb = wm * 64 + i * 16;
                    af[i][0] = Hs[rb + g][kw0 + kb + t];
                    af[i][1] = Hs[rb + g + 8][kw0 + kb + t];
                    af[i][2] = Hs[rb + g][kw0 + kb + t + 4];
                    af[i][3] = Hs[rb + g + 8][kw0 + kb + t + 4];
                }
#pragma unroll
                for (int j = 0; j < 8; j++) {
                    int cb = wn * 64 + j * 8;
                    bf[j][0] = Bs[bb + kb + t][cb + g];
                    bf[j][1] = Bs[bb + kb + t + 4][cb + g];
                }
#pragma unroll
                for (int i = 0; i < 4; i++)
#pragma unroll
                    for (int j = 0; j < 8; j++)
                        mma_f16(acc[i][j], af[i], bf[j]);
            }
            __syncthreads();
        }

        // n-tile epilogue: g_Yh[slot] = fp16(wt * (acc + b2))
#pragma unroll
        for (int i = 0; i < 4; i++) {
            int r0 = m0 + wm * 64 + i * 16 + g;
            int r1 = r0 + 8;
#pragma unroll
            for (int j = 0; j < 8; j++) {
                int col = n0 + wn * 64 + j * 8 + 2 * t;
                float bx = b2[(size_t)e * DOUT + col];
                float by = b2[(size_t)e * DOUT + col + 1];
                if (r0 < M) {
                    *(uint32_t*)(g_Yh + ((size_t)e * NTOK + tok0[i]) * DOUT + col) =
                        pkh2(wt0[i] * (acc[i][j][0] + bx), wt0[i] * (acc[i][j][1] + by));
                }
                if (r1 < M) {
                    *(uint32_t*)(g_Yh + ((size_t)e * NTOK + tok1[i]) * DOUT + col) =
                        pkh2(wt1[i] * (acc[i][j][2] + bx), wt1[i] * (acc[i][j][3] + by));
                }
            }
        }
    }
#undef LDCHUNK1
#undef STCHUNK1
#undef LDCHUNK2
#undef STCHUNK2
}

// ---------------- combine: out[tok] = Yh[slotA] + Yh[slotB] ----------------
__global__ void combine_kernel(float* __restrict__ out) {
    int tok = blockIdx.x, tid = threadIdx.x;
    int sa = g_slot2[2 * tok], sb = g_slot2[2 * tok + 1];
    uint2 ua = ((const uint2*)(g_Yh + (size_t)sa * DOUT))[tid];
    uint2 ub = ((const uint2*)(g_Yh + (size_t)sb * DOUT))[tid];
    float2 a0 = __half22float2(*(__half2*)&ua.x);
    float2 a1 = __half22float2(*(__half2*)&ua.y);
    float2 b0 = __half22float2(*(__half2*)&ub.x);
    float2 b1 = __half22float2(*(__half2*)&ub.y);
    ((float4*)(out + (size_t)tok * DOUT))[tid] =
        make_float4(a0.x + b0.x, a0.y + b0.y, a1.x + b1.x, a1.y + b1.y);
}

// ---------------- launch ----------------
extern "C" void kernel_launch(void* const* d_in, const int* in_sizes, int n_in,
                              void* d_out, int out_size) {
    const float* x  = (const float*)d_in[0];
    const float* Wg = (const float*)d_in[1];
    const float* bg = (const float*)d_in[2];
    const float* W1 = (const float*)d_in[3];
    const float* b1 = (const float*)d_in[4];
    const float* W2 = (const float*)d_in[5];
    const float* b2 = (const float*)d_in[6];

    int N = in_sizes[0] / DIN;   // 16384
    float* out      = (float*)d_out;
    float* gate_out = (float*)d_out + (size_t)N * DOUT;

    cudaFuncSetAttribute(moe_ffn, cudaFuncAttributeMaxDynamicSharedMemorySize, FFN_SMEM_BYTES);

    zcnt_kernel<<<1, 32>>>();
    moe_gate_kernel<<<(N * 32 + 255) / 256, 256>>>(x, Wg, bg, gate_out, N);

    dim3 gf(1, NTOK / BM, NEXP);   // 1 x 128 x 8 (inactive tiles exit)
    moe_ffn<<<gf, 256, FFN_SMEM_BYTES>>>(x, W1, b1, W2, b2);

    combine_kernel<<<N, 256>>>(out);
}

// round 16
// speedup vs baseline: 1.4185x; 1.0410x over previous
#include <cuda_runtime.h>
#include <cuda_fp16.h>
#include <cstdint>

#define NTOK 16384
#define DIN  1024
#define DH   256
#define DOUT 1024
#define NEXP 8

// static device scratch (no runtime allocation)
__device__ int      g_count[NEXP];
__device__ int      g_tok[NEXP * NTOK];
__device__ float    g_wt[NEXP * NTOK];
__device__ int      g_slot2[2 * NTOK];                   // per-token expert slots
__device__ __half   g_Yh[(size_t)NEXP * NTOK * DOUT];    // weighted expert outputs (fp16)
__device__ uint32_t g_W1p[NEXP * (DIN / 2) * DH];        // packed fp16 k-pair W1 (4 MB)
__device__ uint32_t g_W2p[NEXP * (DH / 2) * DOUT];       // packed fp16 k-pair W2 (4 MB)

// ---------------- helpers ----------------
__device__ __forceinline__ uint32_t pkh2(float lo, float hi) {
    __half2 h = __floats2half2_rn(lo, hi);
    return *(uint32_t*)&h;
}

__device__ __forceinline__ uint32_t smem_u32(const void* p) {
    uint32_t a;
    asm("{ .reg .u64 t; cvta.to.shared.u64 t, %1; cvt.u32.u64 %0, t; }" : "=r"(a) : "l"(p));
    return a;
}

__device__ __forceinline__ void mma_f16(float* c, const uint32_t* a, const uint32_t* b) {
    asm volatile(
        "mma.sync.aligned.m16n8k16.row.col.f32.f16.f16.f32 "
        "{%0,%1,%2,%3}, {%4,%5,%6,%7}, {%8,%9}, {%0,%1,%2,%3};\n"
        : "+f"(c[0]), "+f"(c[1]), "+f"(c[2]), "+f"(c[3])
        : "r"(a[0]), "r"(a[1]), "r"(a[2]), "r"(a[3]), "r"(b[0]), "r"(b[1]));
}

#define CPA16(dst, src) \
    asm volatile("cp.async.cg.shared.global [%0], [%1], 16;\n" :: "r"(dst), "l"(src))
#define CP_COMMIT() asm volatile("cp.async.commit_group;\n" ::: "memory")
#define CP_WAIT1()  asm volatile("cp.async.wait_group 1;\n" ::: "memory")
#define CP_WAIT0()  asm volatile("cp.async.wait_group 0;\n" ::: "memory")

// Tiling: block tile 128 tokens; 8 warps (2m x 4n), warp tile 64x64.
// Chunk = 32 k-halves = 16 b32 k-pair words. A double-buffered, B triple-buffered.
#define BM 128
#define BN 256
#define BKW 16
#define ASTR 20
#define BSTR 264
#define HSTR 132
// smem words: As 2*128*20=5120, Bs 3*16*264=12672, Hs 128*132=16896
#define FFN_SMEM_WORDS (2 * BM * ASTR + 3 * BKW * BSTR + BM * HSTR)
#define FFN_SMEM_BYTES (FFN_SMEM_WORDS * 4)             // 138752

// ---------------- kernel: zero expert counters ----------------
__global__ void zcnt_kernel() { if (threadIdx.x < NEXP) g_count[threadIdx.x] = 0; }

// ---------------- weight pack: Wp[r][n] = pkh2(W[2r][n], W[2r+1][n]) --------------
// r = e*(K/2)+kp ; base offset ((e*K)+2*kp)*Nd = 2*Nd*r
__global__ void wpack_kernel(const float* __restrict__ W, uint32_t* __restrict__ Wp, int Nd) {
    int idx = blockIdx.x * blockDim.x + threadIdx.x;
    int n = idx & (Nd - 1);
    int r = idx / Nd;
    const float* base = W + (size_t)r * 2 * Nd + n;
    Wp[idx] = pkh2(base[0], base[Nd]);
}

// ---------------- gate: exact fp32 logits, top-2, softmax, scatter ----------------
__global__ void moe_gate_kernel(const float* __restrict__ x, const float* __restrict__ Wg,
                                const float* __restrict__ bg, float* __restrict__ gate_out, int N) {
    int warp = (blockIdx.x * blockDim.x + threadIdx.x) >> 5;
    int lane = threadIdx.x & 31;
    if (warp >= N) return;
    const float* xr = x + (size_t)warp * DIN;
    float acc[8];
#pragma unroll
    for (int e = 0; e < 8; e++) acc[e] = 0.f;
    for (int k = lane; k < DIN; k += 32) {
        float xv = xr[k];
        const float4* wrow = (const float4*)(Wg + (size_t)k * 8);
        float4 w0 = wrow[0], w1 = wrow[1];
        acc[0] += xv * w0.x; acc[1] += xv * w0.y; acc[2] += xv * w0.z; acc[3] += xv * w0.w;
        acc[4] += xv * w1.x; acc[5] += xv * w1.y; acc[6] += xv * w1.z; acc[7] += xv * w1.w;
    }
#pragma unroll
    for (int off = 16; off; off >>= 1)
#pragma unroll
        for (int e = 0; e < 8; e++) acc[e] += __shfl_xor_sync(0xFFFFFFFFu, acc[e], off);
    if (lane == 0) {
        float lg[8];
#pragma unroll
        for (int e = 0; e < 8; e++) { lg[e] = acc[e] + bg[e]; gate_out[(size_t)warp * 8 + e] = lg[e]; }
        int i0 = 0; float m0 = lg[0];
#pragma unroll
        for (int e = 1; e < 8; e++) if (lg[e] > m0) { m0 = lg[e]; i0 = e; }
        int i1 = -1; float m1 = -1e30f;
#pragma unroll
        for (int e = 0; e < 8; e++) if (e != i0 && lg[e] > m1) { m1 = lg[e]; i1 = e; }
        float e1 = __expf(m1 - m0);
        float inv = 1.f / (1.f + e1);
        int p0 = atomicAdd(&g_count[i0], 1);
        g_tok[i0 * NTOK + p0] = warp; g_wt[i0 * NTOK + p0] = inv;
        g_slot2[2 * warp + 0] = i0 * NTOK + p0;
        int p1 = atomicAdd(&g_count[i1], 1);
        g_tok[i1 * NTOK + p1] = warp; g_wt[i1 * NTOK + p1] = e1 * inv;
        g_slot2[2 * warp + 1] = i1 * NTOK + p1;
    }
}

// ---------------- fused FFN ----------------
__global__ void __launch_bounds__(256, 1)
moe_ffn(const float* __restrict__ x, const float* __restrict__ b1,
        const float* __restrict__ b2) {
    int e = blockIdx.z, m0 = blockIdx.y * BM;
    int M = g_count[e];
    if (m0 >= M) return;

    extern __shared__ uint32_t smem[];
    uint32_t (*As)[ASTR] = (uint32_t(*)[ASTR])smem;                                // [2*BM]
    uint32_t (*Bs)[BSTR] = (uint32_t(*)[BSTR])(smem + 2 * BM * ASTR);              // [3*BKW]
    uint32_t (*Hs)[HSTR] = (uint32_t(*)[HSTR])(smem + 2 * BM * ASTR + 3 * BKW * BSTR); // [BM]
    uint32_t bsb = smem_u32(smem) + (2 * BM * ASTR) * 4;   // byte addr of Bs

    int tid = threadIdx.x, wid = tid >> 5, lane = tid & 31;
    int wm = wid & 1, wn = wid >> 1;
    int g = lane >> 2, t = lane & 3;

    int ar = tid & 127, aw = (tid >> 7) * 8, acf = (tid >> 7) * 16;
    bool aval = (m0 + ar < M);
    const float* arow = x + (size_t)(aval ? g_tok[e * NTOK + m0 + ar] : 0) * DIN + acf;
    int kp = tid >> 4, nb4 = (tid & 15) * 4;

    float acc[4][8][4];
    float4 av[4];

    // B staging via cp.async (4 x 16B per thread per chunk)
#define CPB1(kc, bi) do {                                                          \
        const uint32_t* _src = g_W1p + ((size_t)e * (DIN / 2) + (kc) * 16 + kp) * DH + nb4; \
        uint32_t _dst = bsb + (uint32_t)((((bi) * BKW + kp) * BSTR + nb4) * 4);    \
        _Pragma("unroll")                                                          \
        for (int q = 0; q < 4; q++) CPA16(_dst + q * 256, _src + q * 64);          \
        CP_COMMIT();                                                               \
    } while (0)

#define CPB2(nt, kc, bi) do {                                                      \
        const uint32_t* _src = g_W2p + ((size_t)e * (DH / 2) + (kc) * 16 + kp) * DOUT \
                               + (nt) * BN + nb4;                                  \
        uint32_t _dst = bsb + (uint32_t)((((bi) * BKW + kp) * BSTR + nb4) * 4);    \
        _Pragma("unroll")                                                          \
        for (int q = 0; q < 4; q++) CPA16(_dst + q * 256, _src + q * 64);          \
        CP_COMMIT();                                                               \
    } while (0)

#define LDA1(kc) do {                                                              \
        int _k0 = (kc) * 32;                                                       \
        _Pragma("unroll")                                                          \
        for (int q = 0; q < 4; q++)                                                \
            av[q] = aval ? *(const float4*)(arow + _k0 + q * 4)                    \
                         : make_float4(0.f, 0.f, 0.f, 0.f);                        \
    } while (0)

#define STA1(bi) do {                                                              \
        uint4 _w0, _w1;                                                            \
        _w0.x = pkh2(av[0].x, av[0].y); _w0.y = pkh2(av[0].z, av[0].w);            \
        _w0.z = pkh2(av[1].x, av[1].y); _w0.w = pkh2(av[1].z, av[1].w);            \
        _w1.x = pkh2(av[2].x, av[2].y); _w1.y = pkh2(av[2].z, av[2].w);            \
        _w1.z = pkh2(av[3].x, av[3].y); _w1.w = pkh2(av[3].z, av[3].w);            \
        *(uint4*)&As[(bi) * BM + ar][aw + 0] = _w0;                                \
        *(uint4*)&As[(bi) * BM + ar][aw + 4] = _w1;                                \
    } while (0)

    // ---- phase 1: X @ W1 (K = 1024) ----
#pragma unroll
    for (int i = 0; i < 4; i++)
#pragma unroll
        for (int j = 0; j < 8; j++)
#pragma unroll
            for (int q = 0; q < 4; q++) acc[i][j][q] = 0.f;

    const int NK1 = DIN / 32;   // 32 chunks
    CPB1(0, 0);
    CPB1(1, 1);
    LDA1(0); STA1(0); LDA1(1);

    for (int kc = 0; kc < NK1; kc++) {
        if (kc + 1 < NK1) { CP_WAIT1(); } else { CP_WAIT0(); }
        __syncthreads();
        if (kc + 1 < NK1) {
            STA1((kc + 1) & 1);
            if (kc + 2 < NK1) LDA1(kc + 2);
        }
        if (kc + 2 < NK1) CPB1(kc + 2, (kc + 2) % 3);

        int ab = (kc & 1) * BM, bb = (kc % 3) * BKW;
#pragma unroll
        for (int kk = 0; kk < 2; kk++) {
            int kb = kk * 8;
            uint32_t af[4][4], bf[8][2];
#pragma unroll
            for (int i = 0; i < 4; i++) {
                int rb = ab + wm * 64 + i * 16;
                af[i][0] = As[rb + g][kb + t];
                af[i][1] = As[rb + g + 8][kb + t];
                af[i][2] = As[rb + g][kb + t + 4];
                af[i][3] = As[rb + g + 8][kb + t + 4];
            }
#pragma unroll
            for (int j = 0; j < 8; j++) {
                int cb = wn * 64 + j * 8;
                bf[j][0] = Bs[bb + kb + t][cb + g];
                bf[j][1] = Bs[bb + kb + t + 4][cb + g];
            }
#pragma unroll
            for (int i = 0; i < 4; i++)
#pragma unroll
                for (int j = 0; j < 8; j++)
                    mma_f16(acc[i][j], af[i], bf[j]);
        }
    }
    __syncthreads();

    // phase-1 epilogue: relu(acc + b1) -> Hs (fp16 pairs)
#pragma unroll
    for (int i = 0; i < 4; i++) {
        int r0l = wm * 64 + i * 16 + g;
        int r1l = r0l + 8;
#pragma unroll
        for (int j = 0; j < 8; j++) {
            int col  = wn * 64 + j * 8 + 2 * t;
            int wcol = wn * 32 + j * 4 + t;
            float bx = b1[(size_t)e * DH + col];
            float by = b1[(size_t)e * DH + col + 1];
            Hs[r0l][wcol] = pkh2(fmaxf(acc[i][j][0] + bx, 0.f), fmaxf(acc[i][j][1] + by, 0.f));
            Hs[r1l][wcol] = pkh2(fmaxf(acc[i][j][2] + bx, 0.f), fmaxf(acc[i][j][3] + by, 0.f));
        }
    }
    __syncthreads();

    // ---- phase 2: H @ W2 (K = 256), 4 n-tiles of 256 ----
    int   tok0[4], tok1[4];
    float wt0[4], wt1[4];
#pragma unroll
    for (int i = 0; i < 4; i++) {
        int r0 = m0 + wm * 64 + i * 16 + g;
        int r1 = r0 + 8;
        tok0[i] = 0; tok1[i] = 0; wt0[i] = 0.f; wt1[i] = 0.f;
        if (r0 < M) { tok0[i] = r0; wt0[i] = g_wt[e * NTOK + r0]; }
        if (r1 < M) { tok1[i] = r1; wt1[i] = g_wt[e * NTOK + r1]; }
    }

    const int NK2 = DH / 32;    // 8 chunks
    for (int nt = 0; nt < 4; nt++) {
        CPB2(nt, 0, 0);
        CPB2(nt, 1, 1);
#pragma unroll
        for (int i = 0; i < 4; i++)
#pragma unroll
            for (int j = 0; j < 8; j++)
#pragma unroll
                for (int q = 0; q < 4; q++) acc[i][j][q] = 0.f;

        for (int kc = 0; kc < NK2; kc++) {
            if (kc + 1 < NK2) { CP_WAIT1(); } else { CP_WAIT0(); }
            __syncthreads();
            if (kc + 2 < NK2) CPB2(nt, kc + 2, (kc + 2) % 3);

            int bb = (kc % 3) * BKW;
            int kw0 = kc * 16;
#pragma unroll
            for (int kk = 0; kk < 2; kk++) {
                int kb = kk * 8;
                uint32_t af[4][4], bf[8][2];
#pragma unroll
                for (int i = 0; i < 4; i++) {
                    int rb = wm * 64 + i * 16;
                    af[i][0] = Hs[rb + g][kw0 + kb + t];
                    af[i][1] = Hs[rb + g + 8][kw0 + kb + t];
                    af[i][2] = Hs[rb + g][kw0 + kb + t + 4];
                    af[i][3] = Hs[rb + g + 8][kw0 + kb + t + 4];
                }
#pragma unroll
                for (int j = 0; j < 8; j++) {
                    int cb = wn * 64 + j * 8;
                    bf[j][0] = Bs[bb + kb + t][cb + g];
                    bf[j][1] = Bs[bb + kb + t + 4][cb + g];
                }
#pragma unroll
                for (int i = 0; i < 4; i++)
#pragma unroll
                    for (int j = 0; j < 8; j++)
                        mma_f16(acc[i][j], af[i], bf[j]);
            }
        }
        __syncthreads();   // all B reads done before next nt's cp.async reuses B0/B1

        // n-tile epilogue: g_Yh[slot] = fp16(wt * (acc + b2))
        int n0 = nt * BN;
#pragma unroll
        for (int i = 0; i < 4; i++) {
            int r0 = m0 + wm * 64 + i * 16 + g;
            int r1 = r0 + 8;
#pragma unroll
            for (int j = 0; j < 8; j++) {
                int col = n0 + wn * 64 + j * 8 + 2 * t;
                float bx = b2[(size_t)e * DOUT + col];
                float by = b2[(size_t)e * DOUT + col + 1];
                if (r0 < M) {
                    *(uint32_t*)(g_Yh + ((size_t)e * NTOK + tok0[i]) * DOUT + col) =
                        pkh2(wt0[i] * (acc[i][j][0] + bx), wt0[i] * (acc[i][j][1] + by));
                }
                if (r1 < M) {
                    *(uint32_t*)(g_Yh + ((size_t)e * NTOK + tok1[i]) * DOUT + col) =
                        pkh2(wt1[i] * (acc[i][j][2] + bx), wt1[i] * (acc[i][j][3] + by));
                }
            }
        }
    }
#undef CPB1
#undef CPB2
#undef LDA1
#undef STA1
}

// ---------------- combine: out[tok] = Yh[slotA] + Yh[slotB] ----------------
__global__ void combine_kernel(float* __restrict__ out) {
    int tok = blockIdx.x, tid = threadIdx.x;
    int sa = g_slot2[2 * tok], sb = g_slot2[2 * tok + 1];
    uint2 ua = ((const uint2*)(g_Yh + (size_t)sa * DOUT))[tid];
    uint2 ub = ((const uint2*)(g_Yh + (size_t)sb * DOUT))[tid];
    float2 a0 = __half22float2(*(__half2*)&ua.x);
    float2 a1 = __half22float2(*(__half2*)&ua.y);
    float2 b0 = __half22float2(*(__half2*)&ub.x);
    float2 b1 = __half22float2(*(__half2*)&ub.y);
    ((float4*)(out + (size_t)tok * DOUT))[tid] =
        make_float4(a0.x + b0.x, a0.y + b0.y, a1.x + b1.x, a1.y + b1.y);
}

// ---------------- launch ----------------
extern "C" void kernel_launch(void* const* d_in, const int* in_sizes, int n_in,
                              void* d_out, int out_size) {
    const float* x  = (const float*)d_in[0];
    const float* Wg = (const float*)d_in[1];
    const float* bg = (const float*)d_in[2];
    const float* W1 = (const float*)d_in[3];
    const float* b1 = (const float*)d_in[4];
    const float* W2 = (const float*)d_in[5];
    const float* b2 = (const float*)d_in[6];

    int N = in_sizes[0] / DIN;   // 16384
    float* out      = (float*)d_out;
    float* gate_out = (float*)d_out + (size_t)N * DOUT;

    cudaFuncSetAttribute(moe_ffn, cudaFuncAttributeMaxDynamicSharedMemorySize, FFN_SMEM_BYTES);

    zcnt_kernel<<<1, 32>>>();

    uint32_t* w1p; cudaGetSymbolAddress((void**)&w1p, g_W1p);
    uint32_t* w2p; cudaGetSymbolAddress((void**)&w2p, g_W2p);
    wpack_kernel<<<(NEXP * (DIN / 2) * DH) / 256, 256>>>(W1, w1p, DH);
    wpack_kernel<<<(NEXP * (DH / 2) * DOUT) / 256, 256>>>(W2, w2p, DOUT);

    moe_gate_kernel<<<(N * 32 + 255) / 256, 256>>>(x, Wg, bg, gate_out, N);

    dim3 gf(1, NTOK / BM, NEXP);   // 1 x 128 x 8 (inactive tiles exit)
    moe_ffn<<<gf, 256, FFN_SMEM_BYTES>>>(x, b1, b2);

    combine_kernel<<<N, 256>>>(out);
}

// round 17
// speedup vs baseline: 1.4329x; 1.0102x over previous
#include <cuda_runtime.h>
#include <cuda_fp16.h>
#include <cstdint>

#define NTOK 16384
#define DIN  1024
#define DH   256
#define DOUT 1024
#define NEXP 8

// static device scratch (no runtime allocation)
__device__ int      g_count[NEXP];
__device__ int      g_tok[NEXP * NTOK];
__device__ float    g_wt[NEXP * NTOK];
__device__ int      g_slot2[2 * NTOK];                   // per-token expert slots
__device__ __half   g_Yh[(size_t)NEXP * NTOK * DOUT];    // weighted expert outputs (fp16)
__device__ uint32_t g_W1p[NEXP * (DIN / 2) * DH];        // packed fp16 k-pair W1 (4 MB)
__device__ uint32_t g_W2p[NEXP * (DH / 2) * DOUT];       // packed fp16 k-pair W2 (4 MB)

// ---------------- helpers ----------------
__device__ __forceinline__ uint32_t pkh2(float lo, float hi) {
    __half2 h = __floats2half2_rn(lo, hi);
    return *(uint32_t*)&h;
}

__device__ __forceinline__ uint32_t smem_u32(const void* p) {
    uint32_t a;
    asm("{ .reg .u64 t; cvta.to.shared.u64 t, %1; cvt.u32.u64 %0, t; }" : "=r"(a) : "l"(p));
    return a;
}

__device__ __forceinline__ void mma_f16(float* c, const uint32_t* a, const uint32_t* b) {
    asm volatile(
        "mma.sync.aligned.m16n8k16.row.col.f32.f16.f16.f32 "
        "{%0,%1,%2,%3}, {%4,%5,%6,%7}, {%8,%9}, {%0,%1,%2,%3};\n"
        : "+f"(c[0]), "+f"(c[1]), "+f"(c[2]), "+f"(c[3])
        : "r"(a[0]), "r"(a[1]), "r"(a[2]), "r"(a[3]), "r"(b[0]), "r"(b[1]));
}

#define CPA16(dst, src) \
    asm volatile("cp.async.cg.shared.global [%0], [%1], 16;\n" :: "r"(dst), "l"(src))
#define CP_COMMIT() asm volatile("cp.async.commit_group;\n" ::: "memory")
#define CP_WAIT1()  asm volatile("cp.async.wait_group 1;\n" ::: "memory")
#define CP_WAIT0()  asm volatile("cp.async.wait_group 0;\n" ::: "memory")

// Tiling: block tile 128 tokens; 8 warps (2m x 4n), warp tile 64x64.
// Chunk = 32 k-halves = 16 b32 k-pair words. A double-buffered, B triple-buffered.
#define BM 128
#define BN 256
#define BKW 16
#define ASTR 20
#define BSTR 264
#define HSTR 132
// smem words: As 2*128*20=5120, Bs 3*16*264=12672, Hs 128*132=16896
#define FFN_SMEM_WORDS (2 * BM * ASTR + 3 * BKW * BSTR + BM * HSTR)
#define FFN_SMEM_BYTES (FFN_SMEM_WORDS * 4)             // 138752

// ---------------- kernel: zero expert counters ----------------
__global__ void zcnt_kernel() { if (threadIdx.x < NEXP) g_count[threadIdx.x] = 0; }

// ---------------- weight pack: Wp[r][n] = pkh2(W[2r][n], W[2r+1][n]) --------------
__global__ void wpack_kernel(const float* __restrict__ W, uint32_t* __restrict__ Wp, int Nd) {
    int idx = blockIdx.x * blockDim.x + threadIdx.x;
    int n = idx & (Nd - 1);
    int r = idx / Nd;
    const float* base = W + (size_t)r * 2 * Nd + n;
    Wp[idx] = pkh2(base[0], base[Nd]);
}

// ---------------- gate: 4 tokens per warp; exact fp32; Wg reused 4x ---------------
__global__ void moe_gate_kernel(const float* __restrict__ x, const float* __restrict__ Wg,
                                const float* __restrict__ bg, float* __restrict__ gate_out, int N) {
    int warp = (blockIdx.x * blockDim.x + threadIdx.x) >> 5;
    int lane = threadIdx.x & 31;
    int tok0 = warp * 4;
    if (tok0 >= N) return;
    const float* xr = x + (size_t)tok0 * DIN;

    float acc[4][8];
#pragma unroll
    for (int i = 0; i < 4; i++)
#pragma unroll
        for (int e = 0; e < 8; e++) acc[i][e] = 0.f;

    for (int k = lane; k < DIN; k += 32) {
        const float4* wrow = (const float4*)(Wg + (size_t)k * 8);
        float4 w0 = wrow[0], w1 = wrow[1];
#pragma unroll
        for (int i = 0; i < 4; i++) {
            float xv = xr[(size_t)i * DIN + k];
            acc[i][0] += xv * w0.x; acc[i][1] += xv * w0.y;
            acc[i][2] += xv * w0.z; acc[i][3] += xv * w0.w;
            acc[i][4] += xv * w1.x; acc[i][5] += xv * w1.y;
            acc[i][6] += xv * w1.z; acc[i][7] += xv * w1.w;
        }
    }
#pragma unroll
    for (int off = 16; off; off >>= 1)
#pragma unroll
        for (int i = 0; i < 4; i++)
#pragma unroll
            for (int e = 0; e < 8; e++)
                acc[i][e] += __shfl_xor_sync(0xFFFFFFFFu, acc[i][e], off);

    if (lane == 0) {
#pragma unroll
        for (int i = 0; i < 4; i++) {
            int tok = tok0 + i;
            float lg[8];
#pragma unroll
            for (int e = 0; e < 8; e++) {
                lg[e] = acc[i][e] + bg[e];
                gate_out[(size_t)tok * 8 + e] = lg[e];
            }
            int i0 = 0; float m0 = lg[0];
#pragma unroll
            for (int e = 1; e < 8; e++) if (lg[e] > m0) { m0 = lg[e]; i0 = e; }
            int i1 = -1; float m1 = -1e30f;
#pragma unroll
            for (int e = 0; e < 8; e++) if (e != i0 && lg[e] > m1) { m1 = lg[e]; i1 = e; }
            float e1 = __expf(m1 - m0);
            float inv = 1.f / (1.f + e1);
            int p0 = atomicAdd(&g_count[i0], 1);
            g_tok[i0 * NTOK + p0] = tok; g_wt[i0 * NTOK + p0] = inv;
            g_slot2[2 * tok + 0] = i0 * NTOK + p0;
            int p1 = atomicAdd(&g_count[i1], 1);
            g_tok[i1 * NTOK + p1] = tok; g_wt[i1 * NTOK + p1] = e1 * inv;
            g_slot2[2 * tok + 1] = i1 * NTOK + p1;
        }
    }
}

// ---------------- fused FFN ----------------
__global__ void __launch_bounds__(256, 1)
moe_ffn(const float* __restrict__ x, const float* __restrict__ b1,
        const float* __restrict__ b2) {
    int e = blockIdx.z, m0 = blockIdx.y * BM;
    int M = g_count[e];
    if (m0 >= M) return;

    extern __shared__ uint32_t smem[];
    uint32_t (*As)[ASTR] = (uint32_t(*)[ASTR])smem;                                // [2*BM]
    uint32_t (*Bs)[BSTR] = (uint32_t(*)[BSTR])(smem + 2 * BM * ASTR);              // [3*BKW]
    uint32_t (*Hs)[HSTR] = (uint32_t(*)[HSTR])(smem + 2 * BM * ASTR + 3 * BKW * BSTR); // [BM]
    uint32_t bsb = smem_u32(smem) + (2 * BM * ASTR) * 4;   // byte addr of Bs

    int tid = threadIdx.x, wid = tid >> 5, lane = tid & 31;
    int wm = wid & 1, wn = wid >> 1;
    int g = lane >> 2, t = lane & 3;

    int ar = tid & 127, aw = (tid >> 7) * 8, acf = (tid >> 7) * 16;
    bool aval = (m0 + ar < M);
    const float* arow = x + (size_t)(aval ? g_tok[e * NTOK + m0 + ar] : 0) * DIN + acf;
    int kp = tid >> 4, nb4 = (tid & 15) * 4;

    float acc[4][8][4];
    float4 av[4];

#define CPB1(kc, bi) do {                                                          \
        const uint32_t* _src = g_W1p + ((size_t)e * (DIN / 2) + (kc) * 16 + kp) * DH + nb4; \
        uint32_t _dst = bsb + (uint32_t)((((bi) * BKW + kp) * BSTR + nb4) * 4);    \
        _Pragma("unroll")                                                          \
        for (int q = 0; q < 4; q++) CPA16(_dst + q * 256, _src + q * 64);          \
        CP_COMMIT();                                                               \
    } while (0)

#define CPB2(nt, kc, bi) do {                                                      \
        const uint32_t* _src = g_W2p + ((size_t)e * (DH / 2) + (kc) * 16 + kp) * DOUT \
                               + (nt) * BN + nb4;                                  \
        uint32_t _dst = bsb + (uint32_t)((((bi) * BKW + kp) * BSTR + nb4) * 4);    \
        _Pragma("unroll")                                                          \
        for (int q = 0; q < 4; q++) CPA16(_dst + q * 256, _src + q * 64);          \
        CP_COMMIT();                                                               \
    } while (0)

#define LDA1(kc) do {                                                              \
        int _k0 = (kc) * 32;                                                       \
        _Pragma("unroll")                                                          \
        for (int q = 0; q < 4; q++)                                                \
            av[q] = aval ? *(const float4*)(arow + _k0 + q * 4)                    \
                         : make_float4(0.f, 0.f, 0.f, 0.f);                        \
    } while (0)

#define STA1(bi) do {                                                              \
        uint4 _w0, _w1;                                                            \
        _w0.x = pkh2(av[0].x, av[0].y); _w0.y = pkh2(av[0].z, av[0].w);            \
        _w0.z = pkh2(av[1].x, av[1].y); _w0.w = pkh2(av[1].z, av[1].w);            \
        _w1.x = pkh2(av[2].x, av[2].y); _w1.y = pkh2(av[2].z, av[2].w);            \
        _w1.z = pkh2(av[3].x, av[3].y); _w1.w = pkh2(av[3].z, av[3].w);            \
        *(uint4*)&As[(bi) * BM + ar][aw + 0] = _w0;                                \
        *(uint4*)&As[(bi) * BM + ar][aw + 4] = _w1;                                \
    } while (0)

    // ---- phase 1: X @ W1 (K = 1024) ----
#pragma unroll
    for (int i = 0; i < 4; i++)
#pragma unroll
        for (int j = 0; j < 8; j++)
#pragma unroll
            for (int q = 0; q < 4; q++) acc[i][j][q] = 0.f;

    const int NK1 = DIN / 32;   // 32 chunks
    CPB1(0, 0);
    CPB1(1, 1);
    LDA1(0); STA1(0); LDA1(1);

    for (int kc = 0; kc < NK1; kc++) {
        if (kc + 1 < NK1) { CP_WAIT1(); } else { CP_WAIT0(); }
        __syncthreads();
        if (kc + 1 < NK1) {
            STA1((kc + 1) & 1);
            if (kc + 2 < NK1) LDA1(kc + 2);
        }
        if (kc + 2 < NK1) CPB1(kc + 2, (kc + 2) % 3);

        int ab = (kc & 1) * BM, bb = (kc % 3) * BKW;
#pragma unroll
        for (int kk = 0; kk < 2; kk++) {
            int kb = kk * 8;
            uint32_t af[4][4], bf[8][2];
#pragma unroll
            for (int i = 0; i < 4; i++) {
                int rb = ab + wm * 64 + i * 16;
                af[i][0] = As[rb + g][kb + t];
                af[i][1] = As[rb + g + 8][kb + t];
                af[i][2] = As[rb + g][kb + t + 4];
                af[i][3] = As[rb + g + 8][kb + t + 4];
            }
#pragma unroll
            for (int j = 0; j < 8; j++) {
                int cb = wn * 64 + j * 8;
                bf[j][0] = Bs[bb + kb + t][cb + g];
                bf[j][1] = Bs[bb + kb + t + 4][cb + g];
            }
#pragma unroll
            for (int i = 0; i < 4; i++)
#pragma unroll
                for (int j = 0; j < 8; j++)
                    mma_f16(acc[i][j], af[i], bf[j]);
        }
    }
    __syncthreads();

    // phase-1 epilogue: relu(acc + b1) -> Hs (fp16 pairs)
#pragma unroll
    for (int i = 0; i < 4; i++) {
        int r0l = wm * 64 + i * 16 + g;
        int r1l = r0l + 8;
#pragma unroll
        for (int j = 0; j < 8; j++) {
            int col  = wn * 64 + j * 8 + 2 * t;
            int wcol = wn * 32 + j * 4 + t;
            float bx = b1[(size_t)e * DH + col];
            float by = b1[(size_t)e * DH + col + 1];
            Hs[r0l][wcol] = pkh2(fmaxf(acc[i][j][0] + bx, 0.f), fmaxf(acc[i][j][1] + by, 0.f));
            Hs[r1l][wcol] = pkh2(fmaxf(acc[i][j][2] + bx, 0.f), fmaxf(acc[i][j][3] + by, 0.f));
        }
    }
    __syncthreads();

    // ---- phase 2: H @ W2 (K = 256), 4 n-tiles of 256 ----
    int   tok0[4], tok1[4];
    float wt0[4], wt1[4];
#pragma unroll
    for (int i = 0; i < 4; i++) {
        int r0 = m0 + wm * 64 + i * 16 + g;
        int r1 = r0 + 8;
        tok0[i] = 0; tok1[i] = 0; wt0[i] = 0.f; wt1[i] = 0.f;
        if (r0 < M) { tok0[i] = r0; wt0[i] = g_wt[e * NTOK + r0]; }
        if (r1 < M) { tok1[i] = r1; wt1[i] = g_wt[e * NTOK + r1]; }
    }

    const int NK2 = DH / 32;    // 8 chunks
    for (int nt = 0; nt < 4; nt++) {
        CPB2(nt, 0, 0);
        CPB2(nt, 1, 1);
#pragma unroll
        for (int i = 0; i < 4; i++)
#pragma unroll
            for (int j = 0; j < 8; j++)
#pragma unroll
                for (int q = 0; q < 4; q++) acc[i][j][q] = 0.f;

        for (int kc = 0; kc < NK2; kc++) {
            if (kc + 1 < NK2) { CP_WAIT1(); } else { CP_WAIT0(); }
            __syncthreads();
            if (kc + 2 < NK2) CPB2(nt, kc + 2, (kc + 2) % 3);

            int bb = (kc % 3) * BKW;
            int kw0 = kc * 16;
#pragma unroll
            for (int kk = 0; kk < 2; kk++) {
                int kb = kk * 8;
                uint32_t af[4][4], bf[8][2];
#pragma unroll
                for (int i = 0; i < 4; i++) {
                    int rb = wm * 64 + i * 16;
                    af[i][0] = Hs[rb + g][kw0 + kb + t];
                    af[i][1] = Hs[rb + g + 8][kw0 + kb + t];
                    af[i][2] = Hs[rb + g][kw0 + kb + t + 4];
                    af[i][3] = Hs[rb + g + 8][kw0 + kb + t + 4];
                }
#pragma unroll
                for (int j = 0; j < 8; j++) {
                    int cb = wn * 64 + j * 8;
                    bf[j][0] = Bs[bb + kb + t][cb + g];
                    bf[j][1] = Bs[bb + kb + t + 4][cb + g];
                }
#pragma unroll
                for (int i = 0; i < 4; i++)
#pragma unroll
                    for (int j = 0; j < 8; j++)
                        mma_f16(acc[i][j], af[i], bf[j]);
            }
        }
        __syncthreads();   // all B reads done before next nt's cp.async reuses B0/B1

        // n-tile epilogue: g_Yh[slot] = fp16(wt * (acc + b2))
        int n0 = nt * BN;
#pragma unroll
        for (int i = 0; i < 4; i++) {
            int r0 = m0 + wm * 64 + i * 16 + g;
            int r1 = r0 + 8;
#pragma unroll
            for (int j = 0; j < 8; j++) {
                int col = n0 + wn * 64 + j * 8 + 2 * t;
                float bx = b2[(size_t)e * DOUT + col];
                float by = b2[(size_t)e * DOUT + col + 1];
                if (r0 < M) {
                    *(uint32_t*)(g_Yh + ((size_t)e * NTOK + tok0[i]) * DOUT + col) =
                        pkh2(wt0[i] * (acc[i][j][0] + bx), wt0[i] * (acc[i][j][1] + by));
                }
                if (r1 < M) {
                    *(uint32_t*)(g_Yh + ((size_t)e * NTOK + tok1[i]) * DOUT + col) =
                        pkh2(wt1[i] * (acc[i][j][2] + bx), wt1[i] * (acc[i][j][3] + by));
                }
            }
        }
    }
#undef CPB1
#undef CPB2
#undef LDA1
#undef STA1
}

// ---------------- combine: out[tok] = Yh[slotA] + Yh[slotB] ----------------
__global__ void combine_kernel(float* __restrict__ out) {
    int tok = blockIdx.x, tid = threadIdx.x;
    int sa = g_slot2[2 * tok], sb = g_slot2[2 * tok + 1];
    uint2 ua = ((const uint2*)(g_Yh + (size_t)sa * DOUT))[tid];
    uint2 ub = ((const uint2*)(g_Yh + (size_t)sb * DOUT))[tid];
    float2 a0 = __half22float2(*(__half2*)&ua.x);
    float2 a1 = __half22float2(*(__half2*)&ua.y);
    float2 b0 = __half22float2(*(__half2*)&ub.x);
    float2 b1 = __half22float2(*(__half2*)&ub.y);
    ((float4*)(out + (size_t)tok * DOUT))[tid] =
        make_float4(a0.x + b0.x, a0.y + b0.y, a1.x + b1.x, a1.y + b1.y);
}

// ---------------- launch ----------------
extern "C" void kernel_launch(void* const* d_in, const int* in_sizes, int n_in,
                              void* d_out, int out_size) {
    const float* x  = (const float*)d_in[0];
    const float* Wg = (const float*)d_in[1];
    const float* bg = (const float*)d_in[2];
    const float* W1 = (const float*)d_in[3];
    const float* b1 = (const float*)d_in[4];
    const float* W2 = (const float*)d_in[5];
    const float* b2 = (const float*)d_in[6];

    int N = in_sizes[0] / DIN;   // 16384
    float* out      = (float*)d_out;
    float* gate_out = (float*)d_out + (size_t)N * DOUT;

    cudaFuncSetAttribute(moe_ffn, cudaFuncAttributeMaxDynamicSharedMemorySize, FFN_SMEM_BYTES);

    zcnt_kernel<<<1, 32>>>();

    uint32_t* w1p; cudaGetSymbolAddress((void**)&w1p, g_W1p);
    uint32_t* w2p; cudaGetSymbolAddress((void**)&w2p, g_W2p);
    wpack_kernel<<<(NEXP * (DIN / 2) * DH) / 256, 256>>>(W1, w1p, DH);
    wpack_kernel<<<(NEXP * (DH / 2) * DOUT) / 256, 256>>>(W2, w2p, DOUT);

    moe_gate_kernel<<<(N / 4 * 32 + 255) / 256, 256>>>(x, Wg, bg, gate_out, N);

    dim3 gf(1, NTOK / BM, NEXP);   // 1 x 128 x 8 (inactive tiles exit)
    moe_ffn<<<gf, 256, FFN_SMEM_BYTES>>>(x, b1, b2);

    combine_kernel<<<N, 256>>>(out);
}